// round 3
// baseline (speedup 1.0000x reference)
#include <cuda_runtime.h>
#include <math_constants.h>

#define B_  2
#define S_  2048
#define D_  1024
#define H_  16
#define HD_ 64

// Q plain [bh][s][d] (pre-scaled). K packed hi/lo b-frags. V packed 4-row frags.
__device__ float  g_Q [B_ * H_ * S_ * HD_];
__device__ float4 g_K4[B_ * H_ * S_ * 32];        // [bh][kcol][slot=kk*4+t]
__device__ float4 g_V4[B_ * H_ * (S_ / 4) * 64];  // [bh][j][d]

__device__ __forceinline__ unsigned f2tf(float x) {
    unsigned r;
    asm("cvt.rna.tf32.f32 %0, %1;" : "=r"(r) : "f"(x));
    return r;
}
__device__ __forceinline__ float tf2f(unsigned u) { return __uint_as_float(u); }
__device__ __forceinline__ float tfr(float x) { return tf2f(f2tf(x)); }

__device__ __forceinline__ void mma8(float c[4], const unsigned a[4],
                                     unsigned b0, unsigned b1) {
    asm volatile(
        "mma.sync.aligned.m16n8k8.row.col.f32.tf32.tf32.f32 "
        "{%0,%1,%2,%3},{%4,%5,%6,%7},{%8,%9},{%0,%1,%2,%3};"
        : "+f"(c[0]), "+f"(c[1]), "+f"(c[2]), "+f"(c[3])
        : "r"(a[0]), "r"(a[1]), "r"(a[2]), "r"(a[3]), "r"(b0), "r"(b1));
}

// ---------------------------------------------------------------------------
// QKV projection, 3xTF32, 128x128x16 tiles, fragments pre-packed in smem.
// 256 threads = 8 warps (4m x 2n), warp tile 32x64.
// ---------------------------------------------------------------------------
__global__ __launch_bounds__(256) void qkv_kernel(
    const float* __restrict__ X,
    const float* __restrict__ Wq, const float* __restrict__ Wk, const float* __restrict__ Wv,
    const float* __restrict__ bq, const float* __restrict__ bk, const float* __restrict__ bv)
{
    const int z = blockIdx.z;
    const float* W    = (z == 0) ? Wq : (z == 1) ? Wk : Wv;
    const float* bias = (z == 0) ? bq : (z == 1) ? bk : bv;

    __shared__ float4 A4h[512], A4l[512], B4[1024];
    float* A4hf = (float*)A4h;
    float* A4lf = (float*)A4l;
    float* B4f  = (float*)B4;

    const int tid  = threadIdx.x;
    const int lane = tid & 31;
    const int warp = tid >> 5;
    const int wm = warp & 3;
    const int wn = warp >> 2;
    const int rowBase = blockIdx.y * 128;
    const int colBase = blockIdx.x * 128;
    const int g = lane >> 2;
    const int t = lane & 3;

    float acc[2][8][4];
    #pragma unroll
    for (int mt = 0; mt < 2; mt++)
        #pragma unroll
        for (int nt = 0; nt < 8; nt++)
            #pragma unroll
            for (int i = 0; i < 4; i++) acc[mt][nt][i] = 0.0f;

    for (int k0 = 0; k0 < D_; k0 += 16) {
        __syncthreads();
        // A tile 128x16 -> packed a-frags (hi, lo)
        #pragma unroll
        for (int i = 0; i < 2; i++) {
            const int idx = i * 256 + tid;
            const int r  = idx >> 2;
            const int c4 = (idx & 3) * 4;
            float4 v = *(const float4*)&X[(size_t)(rowBase + r) * D_ + k0 + c4];
            float vv[4] = {v.x, v.y, v.z, v.w};
            const int mG = r >> 4, gg = r & 7, hb = (r >> 3) & 1;
            #pragma unroll
            for (int j = 0; j < 4; j++) {
                const int c = c4 + j, kk = c >> 3, tt = c & 7;
                const int wo = hb + ((tt >= 4) ? 2 : 0);
                const int i4 = ((kk * 8 + mG) * 8 + gg) * 4 + (tt & 3);
                float hi = tfr(vv[j]);
                A4hf[i4 * 4 + wo] = hi;
                A4lf[i4 * 4 + wo] = tfr(vv[j] - hi);
            }
        }
        // B tile 16x128 -> packed b-frags (hi+lo in one float4)
        #pragma unroll
        for (int i = 0; i < 2; i++) {
            const int idx = i * 256 + tid;
            const int kr = idx >> 5;
            const int c4 = (idx & 31) * 4;
            float4 v = *(const float4*)&W[(size_t)(k0 + kr) * D_ + colBase + c4];
            float vv[4] = {v.x, v.y, v.z, v.w};
            const int kk = kr >> 3, tt = kr & 7, tl = tt & 3, hb = tt >> 2;
            #pragma unroll
            for (int j = 0; j < 4; j++) {
                const int c = c4 + j;
                const int i4 = ((kk * 16 + (c >> 3)) * 8 + (c & 7)) * 4 + tl;
                float hi = tfr(vv[j]);
                B4f[i4 * 4 + hb]     = hi;
                B4f[i4 * 4 + 2 + hb] = tfr(vv[j] - hi);
            }
        }
        __syncthreads();

        #pragma unroll
        for (int kk = 0; kk < 2; kk++) {
            float4 ah[2], al[2];
            #pragma unroll
            for (int mt = 0; mt < 2; mt++) {
                const int mG = wm * 2 + mt;
                ah[mt] = A4h[((kk * 8 + mG) * 8 + g) * 4 + t];
                al[mt] = A4l[((kk * 8 + mG) * 8 + g) * 4 + t];
            }
            #pragma unroll
            for (int nt = 0; nt < 8; nt++) {
                float4 bb = B4[((kk * 16 + wn * 8 + nt) * 8 + g) * 4 + t];
                const unsigned bh0 = __float_as_uint(bb.x), bh1 = __float_as_uint(bb.y);
                const unsigned bl0 = __float_as_uint(bb.z), bl1 = __float_as_uint(bb.w);
                #pragma unroll
                for (int mt = 0; mt < 2; mt++) {
                    unsigned ahr[4] = {__float_as_uint(ah[mt].x), __float_as_uint(ah[mt].y),
                                       __float_as_uint(ah[mt].z), __float_as_uint(ah[mt].w)};
                    unsigned alr[4] = {__float_as_uint(al[mt].x), __float_as_uint(al[mt].y),
                                       __float_as_uint(al[mt].z), __float_as_uint(al[mt].w)};
                    mma8(acc[mt][nt], ahr, bh0, bh1);
                    mma8(acc[mt][nt], ahr, bl0, bl1);
                    mma8(acc[mt][nt], alr, bh0, bh1);
                }
            }
        }
    }

    // Epilogue: bias, then scatter to the attn-ready layouts
    float* gK = (float*)g_K4;
    float* gV = (float*)g_V4;
    #pragma unroll
    for (int mt = 0; mt < 2; mt++) {
        #pragma unroll
        for (int nt = 0; nt < 8; nt++) {
            #pragma unroll
            for (int i = 0; i < 4; i++) {
                const int m = rowBase + wm * 32 + mt * 16 + g + ((i >> 1) ? 8 : 0);
                const int n = colBase + wn * 64 + nt * 8 + 2 * t + (i & 1);
                const int b = m >> 11, s = m & (S_ - 1);
                const int h = n >> 6, d = n & (HD_ - 1);
                const int bh = b * H_ + h;
                const float v = acc[mt][nt][i] + bias[n];
                if (z == 0) {
                    g_Q[((size_t)bh * S_ + s) * HD_ + d] = v * 0.125f;
                } else if (z == 1) {
                    const float hi = tfr(v);
                    const float lo = tfr(v - hi);
                    const int dd = d & 7;
                    const int slot = (d >> 3) * 4 + (dd & 3);
                    const size_t base = (((size_t)bh * S_ + s) * 32 + slot) * 4;
                    const int hw = (dd < 4) ? 0 : 1;
                    gK[base + hw]     = hi;
                    gK[base + 2 + hw] = lo;
                } else {
                    const int j  = (s >> 4) * 4 + (s & 3);
                    const int wo = ((s >> 2) & 1) + 2 * ((s >> 3) & 1);
                    gV[(((size_t)bh * (S_ / 4) + j) * 64 + d) * 4 + wo] = tfr(v);
                }
            }
        }
    }
}

// ---------------------------------------------------------------------------
// Flash attention. Block = 64 queries x (b,h). 128 threads / 4 warps.
// All fragments arrive via single LDS.128; P repacked with quad shuffles.
// ---------------------------------------------------------------------------
#define KLD 36   // K smem row stride in float4
#define VLD 66   // V smem row stride in float4
__global__ __launch_bounds__(128) void attn_kernel(
    const float* __restrict__ mask, float* __restrict__ out)
{
    extern __shared__ float4 sm4[];
    float4* K4s = sm4;                       // 64 x 36 = 2304
    float4* V4s = sm4 + 2304;                // 16 x 66 = 1056
    float4* Pq  = sm4 + 2304 + 1056;         // 4 warps x 256
    float*  msk = (float*)(sm4 + 2304 + 1056 + 1024);  // 2048 floats
    float*  Qst = (float*)K4s;               // overlay: Q staging, stride 68

    const int tid  = threadIdx.x;
    const int lane = tid & 31;
    const int warp = tid >> 5;
    const int g = lane >> 2;
    const int t = lane & 3;
    const int qBase = blockIdx.x * 64;
    const int bh = blockIdx.y;
    const int b = bh >> 4;
    const int h = bh & 15;

    // mask row -> smem
    #pragma unroll
    for (int i = 0; i < 4; i++) {
        const int idx = i * 128 + tid;
        ((float4*)msk)[idx] = ((const float4*)(mask + (size_t)b * S_))[idx];
    }
    // Q tile -> staging (overlaid on K smem)
    const float* Qp = g_Q + (size_t)bh * S_ * HD_;
    #pragma unroll
    for (int i = 0; i < 8; i++) {
        const int idx = i * 128 + tid;
        const int r = idx >> 4, c = idx & 15;
        *(float4*)&Qst[r * 68 + c * 4] = *(const float4*)&Qp[(size_t)(qBase + r) * HD_ + c * 4];
    }
    __syncthreads();

    unsigned qh[8][4], ql[8][4];
    const int qr = warp * 16 + g;
    #pragma unroll
    for (int kk = 0; kk < 8; kk++) {
        const int c0 = kk * 8 + t;
        float f[4] = {Qst[qr * 68 + c0], Qst[(qr + 8) * 68 + c0],
                      Qst[qr * 68 + c0 + 4], Qst[(qr + 8) * 68 + c0 + 4]};
        #pragma unroll
        for (int i = 0; i < 4; i++) {
            qh[kk][i] = f2tf(f[i]);
            ql[kk][i] = f2tf(f[i] - tf2f(qh[kk][i]));
        }
    }

    float m_run0 = -CUDART_INF_F, m_run1 = -CUDART_INF_F;
    float l_run0 = 0.0f, l_run1 = 0.0f;
    float o[8][4];
    #pragma unroll
    for (int nt = 0; nt < 8; nt++)
        #pragma unroll
        for (int i = 0; i < 4; i++) o[nt][i] = 0.0f;

    const float4* gK = g_K4 + (size_t)bh * S_ * 32;
    const float4* gV = g_V4 + (size_t)bh * (S_ / 4) * 64;
    float4* Pw = Pq + warp * 256;

    for (int kt = 0; kt < S_ / 64; kt++) {
        __syncthreads();   // prior tile fully consumed (covers Q-staging overlay too)
        // K tile: 64 rows x 32 frags
        #pragma unroll
        for (int i = 0; i < 16; i++) {
            const int idx = i * 128 + tid;
            K4s[(idx >> 5) * KLD + (idx & 31)] = gK[(size_t)kt * 2048 + idx];
        }
        // V tile: 16 rows x 64 frags
        #pragma unroll
        for (int i = 0; i < 8; i++) {
            const int idx = i * 128 + tid;
            V4s[(idx >> 6) * VLD + (idx & 63)] = gV[(size_t)kt * 1024 + idx];
        }
        __syncthreads();

        // S = Q K^T (3xTF32); b-frag = one LDS.128
        float s[8][4];
        #pragma unroll
        for (int nt = 0; nt < 8; nt++)
            #pragma unroll
            for (int i = 0; i < 4; i++) s[nt][i] = 0.0f;

        #pragma unroll
        for (int kk = 0; kk < 8; kk++) {
            #pragma unroll
            for (int nt = 0; nt < 8; nt++) {
                float4 kb = K4s[(nt * 8 + g) * KLD + kk * 4 + t];
                const unsigned bh0 = __float_as_uint(kb.x), bh1 = __float_as_uint(kb.y);
                const unsigned bl0 = __float_as_uint(kb.z), bl1 = __float_as_uint(kb.w);
                mma8(s[nt], qh[kk], bh0, bh1);
                mma8(s[nt], qh[kk], bl0, bl1);
                mma8(s[nt], ql[kk], bh0, bh1);
            }
        }

        // mask add
        const int kBase = kt * 64;
        #pragma unroll
        for (int nt = 0; nt < 8; nt++) {
            const int c = kBase + nt * 8 + 2 * t;
            const float mk0 = msk[c], mk1 = msk[c + 1];
            s[nt][0] += mk0; s[nt][1] += mk1;
            s[nt][2] += mk0; s[nt][3] += mk1;
        }

        // Online softmax
        float mx0 = -CUDART_INF_F, mx1 = -CUDART_INF_F;
        #pragma unroll
        for (int nt = 0; nt < 8; nt++) {
            mx0 = fmaxf(mx0, fmaxf(s[nt][0], s[nt][1]));
            mx1 = fmaxf(mx1, fmaxf(s[nt][2], s[nt][3]));
        }
        mx0 = fmaxf(mx0, __shfl_xor_sync(0xffffffffu, mx0, 1));
        mx0 = fmaxf(mx0, __shfl_xor_sync(0xffffffffu, mx0, 2));
        mx1 = fmaxf(mx1, __shfl_xor_sync(0xffffffffu, mx1, 1));
        mx1 = fmaxf(mx1, __shfl_xor_sync(0xffffffffu, mx1, 2));

        const float mn0 = fmaxf(m_run0, mx0);
        const float mn1 = fmaxf(m_run1, mx1);
        const float corr0 = __expf(m_run0 - mn0);
        const float corr1 = __expf(m_run1 - mn1);

        float sum0 = 0.0f, sum1 = 0.0f;
        #pragma unroll
        for (int nt = 0; nt < 8; nt++) {
            s[nt][0] = __expf(s[nt][0] - mn0); sum0 += s[nt][0];
            s[nt][1] = __expf(s[nt][1] - mn0); sum0 += s[nt][1];
            s[nt][2] = __expf(s[nt][2] - mn1); sum1 += s[nt][2];
            s[nt][3] = __expf(s[nt][3] - mn1); sum1 += s[nt][3];
        }
        sum0 += __shfl_xor_sync(0xffffffffu, sum0, 1);
        sum0 += __shfl_xor_sync(0xffffffffu, sum0, 2);
        sum1 += __shfl_xor_sync(0xffffffffu, sum1, 1);
        sum1 += __shfl_xor_sync(0xffffffffu, sum1, 2);

        l_run0 = l_run0 * corr0 + sum0;
        l_run1 = l_run1 * corr1 + sum1;
        m_run0 = mn0; m_run1 = mn1;

        #pragma unroll
        for (int nt = 0; nt < 8; nt++) {
            o[nt][0] *= corr0; o[nt][1] *= corr0;
            o[nt][2] *= corr1; o[nt][3] *= corr1;
        }

        // P: quad-shuffle C-frag -> A-frag float4, one STS.128 per nt
        const int cc = ((t & 1) << 1) | (t >> 1);
        #pragma unroll
        for (int nt = 0; nt < 8; nt++) {
            const float x0 = __shfl_xor_sync(0xffffffffu, s[nt][0], 2);
            const float x1 = __shfl_xor_sync(0xffffffffu, s[nt][1], 2);
            const float x2 = __shfl_xor_sync(0xffffffffu, s[nt][2], 2);
            const float x3 = __shfl_xor_sync(0xffffffffu, s[nt][3], 2);
            float4 pk;
            if ((t & 2) == 0) pk = make_float4(s[nt][0], s[nt][2], x0, x2);
            else              pk = make_float4(x1, x3, s[nt][1], s[nt][3]);
            pk.x = tfr(pk.x); pk.y = tfr(pk.y); pk.z = tfr(pk.z); pk.w = tfr(pk.w);
            Pw[(nt * 8 + g) * 4 + cc] = pk;
        }
        __syncwarp();

        // O += P V ; one V LDS.128 feeds 2 mmas
        #pragma unroll
        for (int kk = 0; kk < 8; kk += 2) {
            float4 pa0 = Pw[(kk * 8 + g) * 4 + t];
            float4 pa1 = Pw[((kk + 1) * 8 + g) * 4 + t];
            unsigned pr0[4] = {__float_as_uint(pa0.x), __float_as_uint(pa0.y),
                               __float_as_uint(pa0.z), __float_as_uint(pa0.w)};
            unsigned pr1[4] = {__float_as_uint(pa1.x), __float_as_uint(pa1.y),
                               __float_as_uint(pa1.z), __float_as_uint(pa1.w)};
            #pragma unroll
            for (int nt = 0; nt < 8; nt++) {
                float4 vv = V4s[((kk >> 1) * 4 + t) * VLD + nt * 8 + g];
                mma8(o[nt], pr0, __float_as_uint(vv.x), __float_as_uint(vv.y));
                mma8(o[nt], pr1, __float_as_uint(vv.z), __float_as_uint(vv.w));
            }
        }
    }

    // Finalize
    const float inv0 = 1.0f / l_run0;
    const float inv1 = 1.0f / l_run1;
    const int q0 = qBase + qr;
    #pragma unroll
    for (int nt = 0; nt < 8; nt++) {
        const int d = h * 64 + nt * 8 + 2 * t;
        float2 v0 = make_float2(o[nt][0] * inv0, o[nt][1] * inv0);
        float2 v1 = make_float2(o[nt][2] * inv1, o[nt][3] * inv1);
        *(float2*)&out[((size_t)(b * S_ + q0    )) * D_ + d] = v0;
        *(float2*)&out[((size_t)(b * S_ + q0 + 8)) * D_ + d] = v1;
    }
}

// ---------------------------------------------------------------------------
extern "C" void kernel_launch(void* const* d_in, const int* in_sizes, int n_in,
                              void* d_out, int out_size)
{
    const float* X    = (const float*)d_in[0];
    const float* mask = (const float*)d_in[1];
    const float* Wq   = (const float*)d_in[2];
    const float* bq   = (const float*)d_in[3];
    const float* Wk   = (const float*)d_in[4];
    const float* bk   = (const float*)d_in[5];
    const float* Wv   = (const float*)d_in[6];
    const float* bv   = (const float*)d_in[7];
    float* out = (float*)d_out;

    {
        dim3 grid(D_ / 128, (B_ * S_) / 128, 3);
        qkv_kernel<<<grid, 256>>>(X, Wq, Wk, Wv, bq, bk, bv);
    }
    {
        const int smem = (2304 + 1056 + 1024 + 512) * 16;  // 78336 B
        cudaFuncSetAttribute(attn_kernel,
                             cudaFuncAttributeMaxDynamicSharedMemorySize, smem);
        dim3 grid(S_ / 64, B_ * H_);
        attn_kernel<<<grid, 128, smem>>>(mask, out);
    }
}

// round 4
// speedup vs baseline: 2.3427x; 2.3427x over previous
#include <cuda_runtime.h>
#include <cuda_bf16.h>
#include <math_constants.h>

#define B_  2
#define S_  2048
#define D_  1024
#define H_  16
#define HD_ 64

__device__ float g_Q[B_ * H_ * S_ * HD_];
__device__ float g_K[B_ * H_ * S_ * HD_];
__device__ float g_V[B_ * H_ * S_ * HD_];

__device__ __forceinline__ unsigned f2tf(float x) {
    unsigned r;
    asm("cvt.rna.tf32.f32 %0, %1;" : "=r"(r) : "f"(x));
    return r;
}
__device__ __forceinline__ float tf2f(unsigned u) { return __uint_as_float(u); }
__device__ __forceinline__ float tfr(float x) { return tf2f(f2tf(x)); }

__device__ __forceinline__ float bfhi(float x) {
    return __bfloat162float(__float2bfloat16_rn(x));
}
__device__ __forceinline__ unsigned packbf(float a, float b) {
    __nv_bfloat162 h = __floats2bfloat162_rn(a, b);   // .x = a (low), .y = b (high)
    return *(unsigned*)&h;
}

// tf32 m16n8k8
__device__ __forceinline__ void mma8(float c[4], const unsigned a[4],
                                     unsigned b0, unsigned b1) {
    asm volatile(
        "mma.sync.aligned.m16n8k8.row.col.f32.tf32.tf32.f32 "
        "{%0,%1,%2,%3},{%4,%5,%6,%7},{%8,%9},{%0,%1,%2,%3};"
        : "+f"(c[0]), "+f"(c[1]), "+f"(c[2]), "+f"(c[3])
        : "r"(a[0]), "r"(a[1]), "r"(a[2]), "r"(a[3]), "r"(b0), "r"(b1));
}
// bf16 m16n8k16
__device__ __forceinline__ void mma16(float c[4], const unsigned a[4],
                                      unsigned b0, unsigned b1) {
    asm volatile(
        "mma.sync.aligned.m16n8k16.row.col.f32.bf16.bf16.f32 "
        "{%0,%1,%2,%3},{%4,%5,%6,%7},{%8,%9},{%0,%1,%2,%3};"
        : "+f"(c[0]), "+f"(c[1]), "+f"(c[2]), "+f"(c[3])
        : "r"(a[0]), "r"(a[1]), "r"(a[2]), "r"(a[3]), "r"(b0), "r"(b1));
}

// ---------------------------------------------------------------------------
// QKV projection: 3xBF16-split, 128x128x16 tiles, register-staged pipeline.
// 256 threads = 8 warps (4m x 2n), warp tile 32x64.
// Smem: packed bf16x2 pairs, Ah[c][m] = pack(X[m][2c],X[m][2c+1]).
// ---------------------------------------------------------------------------
#define QLDA 136
__global__ __launch_bounds__(256) void qkv_kernel(
    const float* __restrict__ X,
    const float* __restrict__ Wq, const float* __restrict__ Wk, const float* __restrict__ Wv,
    const float* __restrict__ bq, const float* __restrict__ bk, const float* __restrict__ bv)
{
    const int z = blockIdx.z;
    const float* W    = (z == 0) ? Wq : (z == 1) ? Wk : Wv;
    const float* bias = (z == 0) ? bq : (z == 1) ? bk : bv;
    float* Out        = (z == 0) ? g_Q : (z == 1) ? g_K : g_V;
    const float scale = (z == 0) ? 0.125f : 1.0f;

    __shared__ unsigned Ah[8][QLDA], Al[8][QLDA];
    __shared__ unsigned Bh[8][QLDA], Bl[8][QLDA];

    const int tid  = threadIdx.x;
    const int lane = tid & 31;
    const int warp = tid >> 5;
    const int wm = warp & 3;
    const int wn = warp >> 2;
    const int rowBase = blockIdx.y * 128;
    const int colBase = blockIdx.x * 128;
    const int g = lane >> 2;
    const int t = lane & 3;

    // staging task coords
    const int aR0 = (tid)       >> 2, aC0 = (tid)       & 3;
    const int aR1 = (tid + 256) >> 2, aC1 = (tid + 256) & 3;
    const int bC  = tid >> 5,  bN4 = tid & 31;

    float acc[2][8][4];
    #pragma unroll
    for (int mt = 0; mt < 2; mt++)
        #pragma unroll
        for (int nt = 0; nt < 8; nt++)
            #pragma unroll
            for (int i = 0; i < 4; i++) acc[mt][nt][i] = 0.0f;

    // prologue load of tile 0
    float4 aReg0 = *(const float4*)&X[(size_t)(rowBase + aR0) * D_ + aC0 * 4];
    float4 aReg1 = *(const float4*)&X[(size_t)(rowBase + aR1) * D_ + aC1 * 4];
    float4 bReg0 = *(const float4*)&W[(size_t)(2 * bC)     * D_ + colBase + bN4 * 4];
    float4 bReg1 = *(const float4*)&W[(size_t)(2 * bC + 1) * D_ + colBase + bN4 * 4];

    for (int k0 = 0; k0 < D_; k0 += 16) {
        __syncthreads();
        // convert + store staged tile to smem
        {
            float fa0[4] = {aReg0.x, aReg0.y, aReg0.z, aReg0.w};
            float fa1[4] = {aReg1.x, aReg1.y, aReg1.z, aReg1.w};
            #pragma unroll
            for (int p = 0; p < 2; p++) {
                float h0 = bfhi(fa0[2*p]), h1 = bfhi(fa0[2*p+1]);
                Ah[aC0 * 2 + p][aR0] = packbf(h0, h1);
                Al[aC0 * 2 + p][aR0] = packbf(fa0[2*p] - h0, fa0[2*p+1] - h1);
                float g0 = bfhi(fa1[2*p]), g1 = bfhi(fa1[2*p+1]);
                Ah[aC1 * 2 + p][aR1] = packbf(g0, g1);
                Al[aC1 * 2 + p][aR1] = packbf(fa1[2*p] - g0, fa1[2*p+1] - g1);
            }
            float fb0[4] = {bReg0.x, bReg0.y, bReg0.z, bReg0.w};
            float fb1[4] = {bReg1.x, bReg1.y, bReg1.z, bReg1.w};
            #pragma unroll
            for (int p = 0; p < 4; p++) {
                float h0 = bfhi(fb0[p]), h1 = bfhi(fb1[p]);
                Bh[bC][bN4 * 4 + p] = packbf(h0, h1);
                Bl[bC][bN4 * 4 + p] = packbf(fb0[p] - h0, fb1[p] - h1);
            }
        }
        __syncthreads();

        // prefetch next tile while computing this one
        if (k0 + 16 < D_) {
            const int kn = k0 + 16;
            aReg0 = *(const float4*)&X[(size_t)(rowBase + aR0) * D_ + kn + aC0 * 4];
            aReg1 = *(const float4*)&X[(size_t)(rowBase + aR1) * D_ + kn + aC1 * 4];
            bReg0 = *(const float4*)&W[(size_t)(kn + 2 * bC)     * D_ + colBase + bN4 * 4];
            bReg1 = *(const float4*)&W[(size_t)(kn + 2 * bC + 1) * D_ + colBase + bN4 * 4];
        }

        unsigned ah[2][4], al[2][4];
        #pragma unroll
        for (int mt = 0; mt < 2; mt++) {
            const int m0 = wm * 32 + mt * 16 + g;
            ah[mt][0] = Ah[t    ][m0];  ah[mt][1] = Ah[t    ][m0 + 8];
            ah[mt][2] = Ah[t + 4][m0];  ah[mt][3] = Ah[t + 4][m0 + 8];
            al[mt][0] = Al[t    ][m0];  al[mt][1] = Al[t    ][m0 + 8];
            al[mt][2] = Al[t + 4][m0];  al[mt][3] = Al[t + 4][m0 + 8];
        }
        #pragma unroll
        for (int nt = 0; nt < 8; nt++) {
            const int nc = wn * 64 + nt * 8 + g;
            unsigned bh0 = Bh[t][nc], bh1 = Bh[t + 4][nc];
            unsigned bl0 = Bl[t][nc], bl1 = Bl[t + 4][nc];
            #pragma unroll
            for (int mt = 0; mt < 2; mt++) {
                mma16(acc[mt][nt], ah[mt], bh0, bh1);
                mma16(acc[mt][nt], ah[mt], bl0, bl1);
                mma16(acc[mt][nt], al[mt], bh0, bh1);
            }
        }
    }

    // Epilogue (R2 style): bias, scale, coalesced-ish scatter to [B,H,S,HD]
    #pragma unroll
    for (int mt = 0; mt < 2; mt++) {
        #pragma unroll
        for (int nt = 0; nt < 8; nt++) {
            const int n0 = colBase + wn * 64 + nt * 8 + 2 * t;
            #pragma unroll
            for (int i = 0; i < 4; i++) {
                const int m = rowBase + wm * 32 + mt * 16 + g + ((i >> 1) ? 8 : 0);
                const int n = n0 + (i & 1);
                const int b = m >> 11;
                const int s = m & (S_ - 1);
                const int h = n >> 6;
                const int d = n & (HD_ - 1);
                Out[(((size_t)(b * H_ + h) * S_) + s) * HD_ + d] =
                    (acc[mt][nt][i] + bias[n]) * scale;
            }
        }
    }
}

// ---------------------------------------------------------------------------
// Flash attention. Block = 64 queries x (b,h). 128 threads / 4 warps.
// QK^T: 3xBF16-k16 (Q frags register-resident, K packed uint4 frags).
// PV:   1xTF32-k8 (V transposed float2 k-pairs, conflict-free).
// ---------------------------------------------------------------------------
#define KSLD 66   // K smem row stride (uint4 units)
#define VLD2 36   // V smem row stride (float2 units)
#define PLD  68   // P / Q-staging stride (floats)
__global__ __launch_bounds__(128) void attn_kernel(
    const float* __restrict__ mask, float* __restrict__ out)
{
    extern __shared__ char smc[];
    uint4*  Ks  = (uint4*)smc;                         // 16 x 66       (16896 B)
    float2* Vp2 = (float2*)(smc + 16896);              // 64 x 36       (18432 B)
    float*  Ps  = (float*)(smc + 16896 + 18432);       // 64 x 68       (17408 B)
    float*  msk = (float*)(smc + 16896 + 18432 + 17408); // 2048        ( 8192 B)

    const int tid  = threadIdx.x;
    const int lane = tid & 31;
    const int warp = tid >> 5;
    const int g = lane >> 2;
    const int t = lane & 3;
    const int qBase = blockIdx.x * 64;
    const int bh = blockIdx.y;
    const int b = bh >> 4;
    const int h = bh & 15;

    const float* Qp = g_Q + (size_t)bh * S_ * HD_;
    const float* Kp = g_K + (size_t)bh * S_ * HD_;
    const float* Vp = g_V + (size_t)bh * S_ * HD_;

    // mask row -> smem
    #pragma unroll
    for (int i = 0; i < 4; i++) {
        const int idx = i * 128 + tid;
        ((float4*)msk)[idx] = ((const float4*)(mask + (size_t)b * S_))[idx];
    }
    // Q tile -> staging (overlaid on Ps)
    #pragma unroll
    for (int i = 0; i < 8; i++) {
        const int idx = i * 128 + tid;
        const int r = idx >> 4, c = idx & 15;
        *(float4*)&Ps[r * PLD + c * 4] = *(const float4*)&Qp[(size_t)(qBase + r) * HD_ + c * 4];
    }
    __syncthreads();

    // Q bf16 hi/lo frags, register-resident. a-frag kk covers dims 16kk..16kk+15.
    unsigned qh[4][4], ql[4][4];
    const int qr = warp * 16 + g;
    #pragma unroll
    for (int kk = 0; kk < 4; kk++) {
        const int c0 = kk * 16 + 2 * t;
        float q00 = Ps[ qr      * PLD + c0], q01 = Ps[ qr      * PLD + c0 + 1];
        float q10 = Ps[(qr + 8) * PLD + c0], q11 = Ps[(qr + 8) * PLD + c0 + 1];
        float q02 = Ps[ qr      * PLD + c0 + 8], q03 = Ps[ qr      * PLD + c0 + 9];
        float q12 = Ps[(qr + 8) * PLD + c0 + 8], q13 = Ps[(qr + 8) * PLD + c0 + 9];
        float h00 = bfhi(q00), h01 = bfhi(q01), h10 = bfhi(q10), h11 = bfhi(q11);
        float h02 = bfhi(q02), h03 = bfhi(q03), h12 = bfhi(q12), h13 = bfhi(q13);
        qh[kk][0] = packbf(h00, h01);             qh[kk][1] = packbf(h10, h11);
        qh[kk][2] = packbf(h02, h03);             qh[kk][3] = packbf(h12, h13);
        ql[kk][0] = packbf(q00 - h00, q01 - h01); ql[kk][1] = packbf(q10 - h10, q11 - h11);
        ql[kk][2] = packbf(q02 - h02, q03 - h03); ql[kk][3] = packbf(q12 - h12, q13 - h13);
    }

    float m_run0 = -CUDART_INF_F, m_run1 = -CUDART_INF_F;
    float l_run0 = 0.0f, l_run1 = 0.0f;
    float o[8][4];
    #pragma unroll
    for (int nt = 0; nt < 8; nt++)
        #pragma unroll
        for (int i = 0; i < 4; i++) o[nt][i] = 0.0f;

    for (int kt = 0; kt < S_ / 64; kt++) {
        const int kBase = kt * 64;
        __syncthreads();   // prior tile fully consumed (and Q staging done)

        // ---- K tile -> packed bf16 hi/lo frags ----
        #pragma unroll
        for (int i = 0; i < 2; i++) {
            const int idx = i * 128 + tid;
            const int kk = idx >> 6, r = idx & 63;
            const float* Kr = Kp + (size_t)(kBase + r) * HD_ + kk * 16;
            float4 f0 = *(const float4*)(Kr);
            float4 f1 = *(const float4*)(Kr + 4);
            float4 f2 = *(const float4*)(Kr + 8);
            float4 f3 = *(const float4*)(Kr + 12);
            float f[16] = {f0.x,f0.y,f0.z,f0.w, f1.x,f1.y,f1.z,f1.w,
                           f2.x,f2.y,f2.z,f2.w, f3.x,f3.y,f3.z,f3.w};
            #pragma unroll
            for (int tt = 0; tt < 4; tt++) {
                float a0 = f[2*tt], a1 = f[2*tt+1], a2 = f[8+2*tt], a3 = f[8+2*tt+1];
                float h0 = bfhi(a0), h1 = bfhi(a1), h2 = bfhi(a2), h3 = bfhi(a3);
                uint4 frag;
                frag.x = packbf(h0, h1);
                frag.y = packbf(h2, h3);
                frag.z = packbf(a0 - h0, a1 - h1);
                frag.w = packbf(a2 - h2, a3 - h3);
                Ks[(kk * 4 + tt) * KSLD + r] = frag;
            }
        }
        // ---- V tile -> transposed tf32 float2 (k, k+4) pairs ----
        #pragma unroll
        for (int i = 0; i < 8; i++) {
            const int idx = i * 128 + tid;
            const int c4 = idx >> 6, r = idx & 63;
            float4 v = *(const float4*)&Vp[(size_t)(kBase + r) * HD_ + c4 * 4];
            float vv[4] = {v.x, v.y, v.z, v.w};
            const int kk = r >> 3, rr = r & 7;
            float* Vf = (float*)Vp2;
            #pragma unroll
            for (int c = 0; c < 4; c++) {
                const int dcol = c4 * 4 + c;
                const int slot = kk * 4 + (rr & 3);
                Vf[(dcol * VLD2 + slot) * 2 + (rr >> 2)] = tfr(vv[c]);
            }
        }
        __syncthreads();

        // ---- S = Q K^T : 3xBF16 ----
        float s[8][4];
        #pragma unroll
        for (int nt = 0; nt < 8; nt++)
            #pragma unroll
            for (int i = 0; i < 4; i++) s[nt][i] = 0.0f;

        #pragma unroll
        for (int kk = 0; kk < 4; kk++) {
            #pragma unroll
            for (int nt = 0; nt < 8; nt++) {
                uint4 kb = Ks[(kk * 4 + t) * KSLD + nt * 8 + g];
                mma16(s[nt], qh[kk], kb.x, kb.y);
                mma16(s[nt], qh[kk], kb.z, kb.w);
                mma16(s[nt], ql[kk], kb.x, kb.y);
            }
        }

        // mask add
        #pragma unroll
        for (int nt = 0; nt < 8; nt++) {
            const int c = kBase + nt * 8 + 2 * t;
            const float mk0 = msk[c], mk1 = msk[c + 1];
            s[nt][0] += mk0; s[nt][1] += mk1;
            s[nt][2] += mk0; s[nt][3] += mk1;
        }

        // ---- online softmax ----
        float mx0 = -CUDART_INF_F, mx1 = -CUDART_INF_F;
        #pragma unroll
        for (int nt = 0; nt < 8; nt++) {
            mx0 = fmaxf(mx0, fmaxf(s[nt][0], s[nt][1]));
            mx1 = fmaxf(mx1, fmaxf(s[nt][2], s[nt][3]));
        }
        mx0 = fmaxf(mx0, __shfl_xor_sync(0xffffffffu, mx0, 1));
        mx0 = fmaxf(mx0, __shfl_xor_sync(0xffffffffu, mx0, 2));
        mx1 = fmaxf(mx1, __shfl_xor_sync(0xffffffffu, mx1, 1));
        mx1 = fmaxf(mx1, __shfl_xor_sync(0xffffffffu, mx1, 2));

        const float mn0 = fmaxf(m_run0, mx0);
        const float mn1 = fmaxf(m_run1, mx1);
        const float corr0 = __expf(m_run0 - mn0);
        const float corr1 = __expf(m_run1 - mn1);

        float sum0 = 0.0f, sum1 = 0.0f;
        #pragma unroll
        for (int nt = 0; nt < 8; nt++) {
            s[nt][0] = __expf(s[nt][0] - mn0); sum0 += s[nt][0];
            s[nt][1] = __expf(s[nt][1] - mn0); sum0 += s[nt][1];
            s[nt][2] = __expf(s[nt][2] - mn1); sum1 += s[nt][2];
            s[nt][3] = __expf(s[nt][3] - mn1); sum1 += s[nt][3];
        }
        sum0 += __shfl_xor_sync(0xffffffffu, sum0, 1);
        sum0 += __shfl_xor_sync(0xffffffffu, sum0, 2);
        sum1 += __shfl_xor_sync(0xffffffffu, sum1, 1);
        sum1 += __shfl_xor_sync(0xffffffffu, sum1, 2);

        l_run0 = l_run0 * corr0 + sum0;
        l_run1 = l_run1 * corr1 + sum1;
        m_run0 = mn0; m_run1 = mn1;

        #pragma unroll
        for (int nt = 0; nt < 8; nt++) {
            o[nt][0] *= corr0; o[nt][1] *= corr0;
            o[nt][2] *= corr1; o[nt][3] *= corr1;
        }

        // ---- P -> smem (tf32, own-warp rows) ----
        #pragma unroll
        for (int nt = 0; nt < 8; nt++) {
            const int c = nt * 8 + 2 * t;
            float2 p0 = make_float2(tfr(s[nt][0]), tfr(s[nt][1]));
            float2 p1 = make_float2(tfr(s[nt][2]), tfr(s[nt][3]));
            *(float2*)&Ps[ qr      * PLD + c] = p0;
            *(float2*)&Ps[(qr + 8) * PLD + c] = p1;
        }
        __syncwarp();

        // ---- O += P V : 1xTF32 ----
        #pragma unroll
        for (int kk = 0; kk < 8; kk++) {
            const int pk = kk * 8 + t;
            unsigned pa[4];
            pa[0] = __float_as_uint(Ps[ qr      * PLD + pk    ]);
            pa[1] = __float_as_uint(Ps[(qr + 8) * PLD + pk    ]);
            pa[2] = __float_as_uint(Ps[ qr      * PLD + pk + 4]);
            pa[3] = __float_as_uint(Ps[(qr + 8) * PLD + pk + 4]);
            #pragma unroll
            for (int nt = 0; nt < 8; nt++) {
                float2 vb = Vp2[(nt * 8 + g) * VLD2 + kk * 4 + t];
                mma8(o[nt], pa, __float_as_uint(vb.x), __float_as_uint(vb.y));
            }
        }
    }

    // Finalize
    const float inv0 = 1.0f / l_run0;
    const float inv1 = 1.0f / l_run1;
    const int q0 = qBase + qr;
    #pragma unroll
    for (int nt = 0; nt < 8; nt++) {
        const int d = h * 64 + nt * 8 + 2 * t;
        float2 v0 = make_float2(o[nt][0] * inv0, o[nt][1] * inv0);
        float2 v1 = make_float2(o[nt][2] * inv1, o[nt][3] * inv1);
        *(float2*)&out[((size_t)(b * S_ + q0    )) * D_ + d] = v0;
        *(float2*)&out[((size_t)(b * S_ + q0 + 8)) * D_ + d] = v1;
    }
}

// ---------------------------------------------------------------------------
extern "C" void kernel_launch(void* const* d_in, const int* in_sizes, int n_in,
                              void* d_out, int out_size)
{
    const float* X    = (const float*)d_in[0];
    const float* mask = (const float*)d_in[1];
    const float* Wq   = (const float*)d_in[2];
    const float* bq   = (const float*)d_in[3];
    const float* Wk   = (const float*)d_in[4];
    const float* bk   = (const float*)d_in[5];
    const float* Wv   = (const float*)d_in[6];
    const float* bv   = (const float*)d_in[7];
    float* out = (float*)d_out;

    {
        dim3 grid(D_ / 128, (B_ * S_) / 128, 3);
        qkv_kernel<<<grid, 256>>>(X, Wq, Wk, Wv, bq, bk, bv);
    }
    {
        const int smem = 16896 + 18432 + 17408 + 8192;   // 60928 B
        cudaFuncSetAttribute(attn_kernel,
                             cudaFuncAttributeMaxDynamicSharedMemorySize, smem);
        dim3 grid(S_ / 64, B_ * H_);
        attn_kernel<<<grid, 128, smem>>>(mask, out);
    }
}

// round 6
// speedup vs baseline: 3.6479x; 1.5572x over previous
#include <cuda_runtime.h>
#include <cuda_bf16.h>
#include <math_constants.h>

#define B_  2
#define S_  2048
#define D_  1024
#define H_  16
#define HD_ 64
#define NT_ 32   // S_/64 tiles

__device__ float g_Q[B_ * H_ * S_ * HD_];
__device__ float g_K[B_ * H_ * S_ * HD_];
__device__ float g_V[B_ * H_ * S_ * HD_];
// packed: K frags [bh][kt][fslot=kk*4+tt][r=0..63] uint4 {b0hi,b1hi,b0lo,b1lo}
__device__ uint4  g_Kp[B_ * H_ * NT_ * 16 * 64];
// packed: V frags [bh][kt][pslot=kk2*4+t][d=0..63] float4 {V[16kk2+t],[+4],[+8],[+12]}
__device__ float4 g_Vp[B_ * H_ * NT_ * 16 * 64];

__device__ __forceinline__ unsigned f2tf(float x) {
    unsigned r;
    asm("cvt.rna.tf32.f32 %0, %1;" : "=r"(r) : "f"(x));
    return r;
}
__device__ __forceinline__ float tf2f(unsigned u) { return __uint_as_float(u); }
__device__ __forceinline__ float tfr(float x) { return tf2f(f2tf(x)); }
__device__ __forceinline__ float bfhi(float x) {
    return __bfloat162float(__float2bfloat16_rn(x));
}
__device__ __forceinline__ unsigned packbf(float a, float b) {
    __nv_bfloat162 h = __floats2bfloat162_rn(a, b);
    return *(unsigned*)&h;
}
__device__ __forceinline__ void mma8(float c[4], const unsigned a[4],
                                     unsigned b0, unsigned b1) {
    asm volatile(
        "mma.sync.aligned.m16n8k8.row.col.f32.tf32.tf32.f32 "
        "{%0,%1,%2,%3},{%4,%5,%6,%7},{%8,%9},{%0,%1,%2,%3};"
        : "+f"(c[0]), "+f"(c[1]), "+f"(c[2]), "+f"(c[3])
        : "r"(a[0]), "r"(a[1]), "r"(a[2]), "r"(a[3]), "r"(b0), "r"(b1));
}
__device__ __forceinline__ void mma16(float c[4], const unsigned a[4],
                                      unsigned b0, unsigned b1) {
    asm volatile(
        "mma.sync.aligned.m16n8k16.row.col.f32.bf16.bf16.f32 "
        "{%0,%1,%2,%3},{%4,%5,%6,%7},{%8,%9},{%0,%1,%2,%3};"
        : "+f"(c[0]), "+f"(c[1]), "+f"(c[2]), "+f"(c[3])
        : "r"(a[0]), "r"(a[1]), "r"(a[2]), "r"(a[3]), "r"(b0), "r"(b1));
}
__device__ __forceinline__ void cpa16(unsigned dst, const void* src) {
    asm volatile("cp.async.cg.shared.global [%0], [%1], 16;" :: "r"(dst), "l"(src));
}

// ---------------------------------------------------------------------------
// QKV projection: 3xBF16-split, 128x128x16, register-staged pipeline.
// ---------------------------------------------------------------------------
#define QLDA 136
__global__ __launch_bounds__(256) void qkv_kernel(
    const float* __restrict__ X,
    const float* __restrict__ Wq, const float* __restrict__ Wk, const float* __restrict__ Wv,
    const float* __restrict__ bq, const float* __restrict__ bk, const float* __restrict__ bv)
{
    const int z = blockIdx.z;
    const float* W    = (z == 0) ? Wq : (z == 1) ? Wk : Wv;
    const float* bias = (z == 0) ? bq : (z == 1) ? bk : bv;
    float* Out        = (z == 0) ? g_Q : (z == 1) ? g_K : g_V;
    const float scale = (z == 0) ? 0.125f : 1.0f;

    __shared__ unsigned Ah[8][QLDA], Al[8][QLDA];
    __shared__ unsigned Bh[8][QLDA], Bl[8][QLDA];

    const int tid  = threadIdx.x;
    const int lane = tid & 31;
    const int warp = tid >> 5;
    const int wm = warp & 3;
    const int wn = warp >> 2;
    const int rowBase = blockIdx.y * 128;
    const int colBase = blockIdx.x * 128;
    const int g = lane >> 2;
    const int t = lane & 3;

    const int aR0 = (tid)       >> 2, aC0 = (tid)       & 3;
    const int aR1 = (tid + 256) >> 2, aC1 = (tid + 256) & 3;
    const int bC  = tid >> 5,  bN4 = tid & 31;

    float acc[2][8][4];
    #pragma unroll
    for (int mt = 0; mt < 2; mt++)
        #pragma unroll
        for (int nt = 0; nt < 8; nt++)
            #pragma unroll
            for (int i = 0; i < 4; i++) acc[mt][nt][i] = 0.0f;

    float4 aReg0 = *(const float4*)&X[(size_t)(rowBase + aR0) * D_ + aC0 * 4];
    float4 aReg1 = *(const float4*)&X[(size_t)(rowBase + aR1) * D_ + aC1 * 4];
    float4 bReg0 = *(const float4*)&W[(size_t)(2 * bC)     * D_ + colBase + bN4 * 4];
    float4 bReg1 = *(const float4*)&W[(size_t)(2 * bC + 1) * D_ + colBase + bN4 * 4];

    for (int k0 = 0; k0 < D_; k0 += 16) {
        __syncthreads();
        {
            float fa0[4] = {aReg0.x, aReg0.y, aReg0.z, aReg0.w};
            float fa1[4] = {aReg1.x, aReg1.y, aReg1.z, aReg1.w};
            #pragma unroll
            for (int p = 0; p < 2; p++) {
                float h0 = bfhi(fa0[2*p]), h1 = bfhi(fa0[2*p+1]);
                Ah[aC0 * 2 + p][aR0] = packbf(h0, h1);
                Al[aC0 * 2 + p][aR0] = packbf(fa0[2*p] - h0, fa0[2*p+1] - h1);
                float g0 = bfhi(fa1[2*p]), g1 = bfhi(fa1[2*p+1]);
                Ah[aC1 * 2 + p][aR1] = packbf(g0, g1);
                Al[aC1 * 2 + p][aR1] = packbf(fa1[2*p] - g0, fa1[2*p+1] - g1);
            }
            float fb0[4] = {bReg0.x, bReg0.y, bReg0.z, bReg0.w};
            float fb1[4] = {bReg1.x, bReg1.y, bReg1.z, bReg1.w};
            #pragma unroll
            for (int p = 0; p < 4; p++) {
                float h0 = bfhi(fb0[p]), h1 = bfhi(fb1[p]);
                Bh[bC][bN4 * 4 + p] = packbf(h0, h1);
                Bl[bC][bN4 * 4 + p] = packbf(fb0[p] - h0, fb1[p] - h1);
            }
        }
        __syncthreads();

        if (k0 + 16 < D_) {
            const int kn = k0 + 16;
            aReg0 = *(const float4*)&X[(size_t)(rowBase + aR0) * D_ + kn + aC0 * 4];
            aReg1 = *(const float4*)&X[(size_t)(rowBase + aR1) * D_ + kn + aC1 * 4];
            bReg0 = *(const float4*)&W[(size_t)(kn + 2 * bC)     * D_ + colBase + bN4 * 4];
            bReg1 = *(const float4*)&W[(size_t)(kn + 2 * bC + 1) * D_ + colBase + bN4 * 4];
        }

        unsigned ah[2][4], al[2][4];
        #pragma unroll
        for (int mt = 0; mt < 2; mt++) {
            const int m0 = wm * 32 + mt * 16 + g;
            ah[mt][0] = Ah[t    ][m0];  ah[mt][1] = Ah[t    ][m0 + 8];
            ah[mt][2] = Ah[t + 4][m0];  ah[mt][3] = Ah[t + 4][m0 + 8];
            al[mt][0] = Al[t    ][m0];  al[mt][1] = Al[t    ][m0 + 8];
            al[mt][2] = Al[t + 4][m0];  al[mt][3] = Al[t + 4][m0 + 8];
        }
        #pragma unroll
        for (int nt = 0; nt < 8; nt++) {
            const int nc = wn * 64 + nt * 8 + g;
            unsigned bh0 = Bh[t][nc], bh1 = Bh[t + 4][nc];
            unsigned bl0 = Bl[t][nc], bl1 = Bl[t + 4][nc];
            #pragma unroll
            for (int mt = 0; mt < 2; mt++) {
                mma16(acc[mt][nt], ah[mt], bh0, bh1);
                mma16(acc[mt][nt], ah[mt], bl0, bl1);
                mma16(acc[mt][nt], al[mt], bh0, bh1);
            }
        }
    }

    #pragma unroll
    for (int mt = 0; mt < 2; mt++) {
        #pragma unroll
        for (int nt = 0; nt < 8; nt++) {
            const int n0 = colBase + wn * 64 + nt * 8 + 2 * t;
            #pragma unroll
            for (int i = 0; i < 4; i++) {
                const int m = rowBase + wm * 32 + mt * 16 + g + ((i >> 1) ? 8 : 0);
                const int n = n0 + (i & 1);
                const int b = m >> 11;
                const int s = m & (S_ - 1);
                const int h = n >> 6;
                const int d = n & (HD_ - 1);
                Out[(((size_t)(b * H_ + h) * S_) + s) * HD_ + d] =
                    (acc[mt][nt][i] + bias[n]) * scale;
            }
        }
    }
}

// ---------------------------------------------------------------------------
// Pack kernel: K -> bf16 hi/lo uint4 frags, V -> transposed tf32 float4 frags.
// ---------------------------------------------------------------------------
__global__ __launch_bounds__(256) void pack_kernel()
{
    const int kt = blockIdx.x;
    const int bh = blockIdx.y;
    const int tid = threadIdx.x;
    const size_t tile = (size_t)(bh * NT_ + kt) * 16 * 64;

    if (tid < 128) {
        const int r  = tid & 63;
        const int kh = tid >> 6;               // 0..1 -> dims [32kh, 32kh+32)
        const float* Kr = g_K + ((size_t)bh * S_ + kt * 64 + r) * HD_ + kh * 32;
        float f[32];
        #pragma unroll
        for (int i = 0; i < 8; i++)
            *(float4*)&f[i * 4] = *(const float4*)&Kr[i * 4];
        #pragma unroll
        for (int q = 0; q < 2; q++) {
            const int kk = 2 * kh + q;
            #pragma unroll
            for (int tt = 0; tt < 4; tt++) {
                float a0 = f[q*16 + 2*tt],     a1 = f[q*16 + 2*tt + 1];
                float a2 = f[q*16 + 2*tt + 8], a3 = f[q*16 + 2*tt + 9];
                float h0 = bfhi(a0), h1 = bfhi(a1), h2 = bfhi(a2), h3 = bfhi(a3);
                uint4 frag;
                frag.x = packbf(h0, h1);
                frag.y = packbf(h2, h3);
                frag.z = packbf(a0 - h0, a1 - h1);
                frag.w = packbf(a2 - h2, a3 - h3);
                g_Kp[tile + (size_t)(kk * 4 + tt) * 64 + r] = frag;
            }
        }
    } else {
        const int j  = tid - 128;
        const int d  = j & 63;
        const int ph = j >> 6;                 // 0..1 -> pslots [8ph, 8ph+8)
        const float* Vb = g_V + ((size_t)bh * S_ + kt * 64) * HD_;
        #pragma unroll
        for (int pi = 0; pi < 8; pi++) {
            const int pslot = ph * 8 + pi;
            const int kk2 = pslot >> 2, t = pslot & 3;
            const int k0 = kk2 * 16 + t;
            float4 v;
            v.x = tfr(Vb[(size_t)(k0     ) * HD_ + d]);
            v.y = tfr(Vb[(size_t)(k0 +  4) * HD_ + d]);
            v.z = tfr(Vb[(size_t)(k0 +  8) * HD_ + d]);
            v.w = tfr(Vb[(size_t)(k0 + 12) * HD_ + d]);
            g_Vp[tile + (size_t)pslot * 64 + d] = v;
        }
    }
}

// ---------------------------------------------------------------------------
// Flash attention: pure-copy mainloop (cp.async double-buffered), P relayout
// via register shuffles. 128 threads / 4 warps.
// ---------------------------------------------------------------------------
#define KSLD 66   // K smem row stride (uint4)
#define VSLD 66   // V smem row stride (float4)  -- rows are 64 wide + pad
#define KBUF_BYTES (16 * KSLD * 16)   // 16896
#define VBUF_BYTES (16 * VSLD * 16)   // 16896
__global__ __launch_bounds__(128) void attn_kernel(
    const float* __restrict__ mask, float* __restrict__ out)
{
    extern __shared__ char smc[];
    uint4*  Ks   = (uint4*)smc;                                  // 2 bufs
    float4* Vs   = (float4*)(smc + 2 * KBUF_BYTES);              // 2 bufs
    float*  msk  = (float*)(smc + 2 * KBUF_BYTES + 2 * VBUF_BYTES); // 2048 f
    float*  Qst  = (float*)(smc + 2 * KBUF_BYTES);               // overlay on Vs

    const int tid  = threadIdx.x;
    const int lane = tid & 31;
    const int warp = tid >> 5;
    const int g = lane >> 2;
    const int t = lane & 3;
    const int qBase = blockIdx.x * 64;
    const int bh = blockIdx.y;
    const int b = bh >> 4;
    const int h = bh & 15;

    unsigned smem_base;
    {
        void* p = smc;
        asm("{ .reg .u64 tmp; cvta.to.shared.u64 tmp, %1; cvt.u32.u64 %0, tmp; }"
            : "=r"(smem_base) : "l"(p));
    }
    const unsigned ks_sm = smem_base;
    const unsigned vs_sm = smem_base + 2 * KBUF_BYTES;

    // ---- prologue: mask + Q staging ----
    #pragma unroll
    for (int i = 0; i < 4; i++) {
        const int idx = i * 128 + tid;
        ((float4*)msk)[idx] = ((const float4*)(mask + (size_t)b * S_))[idx];
    }
    const float* Qp = g_Q + (size_t)bh * S_ * HD_;
    #pragma unroll
    for (int i = 0; i < 8; i++) {
        const int idx = i * 128 + tid;
        const int r = idx >> 4, c = idx & 15;
        *(float4*)&Qst[r * 68 + c * 4] = *(const float4*)&Qp[(size_t)(qBase + r) * HD_ + c * 4];
    }
    __syncthreads();

    unsigned qh[4][4], ql[4][4];
    const int qr = warp * 16 + g;
    #pragma unroll
    for (int kk = 0; kk < 4; kk++) {
        const int c0 = kk * 16 + 2 * t;
        float q00 = Qst[ qr      * 68 + c0], q01 = Qst[ qr      * 68 + c0 + 1];
        float q10 = Qst[(qr + 8) * 68 + c0], q11 = Qst[(qr + 8) * 68 + c0 + 1];
        float q02 = Qst[ qr      * 68 + c0 + 8], q03 = Qst[ qr      * 68 + c0 + 9];
        float q12 = Qst[(qr + 8) * 68 + c0 + 8], q13 = Qst[(qr + 8) * 68 + c0 + 9];
        float h00 = bfhi(q00), h01 = bfhi(q01), h10 = bfhi(q10), h11 = bfhi(q11);
        float h02 = bfhi(q02), h03 = bfhi(q03), h12 = bfhi(q12), h13 = bfhi(q13);
        qh[kk][0] = packbf(h00, h01);             qh[kk][1] = packbf(h10, h11);
        qh[kk][2] = packbf(h02, h03);             qh[kk][3] = packbf(h12, h13);
        ql[kk][0] = packbf(q00 - h00, q01 - h01); ql[kk][1] = packbf(q10 - h10, q11 - h11);
        ql[kk][2] = packbf(q02 - h02, q03 - h03); ql[kk][3] = packbf(q12 - h12, q13 - h13);
    }
    __syncthreads();   // Q staging reads done before cp.async overwrites Vs

    const uint4*  gK = g_Kp + (size_t)bh * NT_ * 1024;
    const float4* gV = g_Vp + (size_t)bh * NT_ * 1024;

    // issue tile 0 into buffer 0
    #pragma unroll
    for (int i = 0; i < 8; i++) {
        const int idx = i * 128 + tid;
        const int fs = idx >> 6, r = idx & 63;
        cpa16(ks_sm + (fs * KSLD + r) * 16, gK + idx);
        cpa16(vs_sm + (fs * VSLD + r) * 16, gV + idx);
    }
    asm volatile("cp.async.commit_group;");

    float m_run0 = -CUDART_INF_F, m_run1 = -CUDART_INF_F;
    float l_run0 = 0.0f, l_run1 = 0.0f;
    float o[8][4];
    #pragma unroll
    for (int nt = 0; nt < 8; nt++)
        #pragma unroll
        for (int i = 0; i < 4; i++) o[nt][i] = 0.0f;

    const int bl  = lane & 28;           // quad base lane
    const int sl0 = bl + (t >> 1);
    const int sl1 = sl0 + 2;
    const bool odd = (t & 1);

    int buf = 0;
    for (int kt = 0; kt < NT_; kt++) {
        if (kt + 1 < NT_) {
            const unsigned ksd = ks_sm + (buf ^ 1) * KBUF_BYTES;
            const unsigned vsd = vs_sm + (buf ^ 1) * VBUF_BYTES;
            const size_t tb = (size_t)(kt + 1) * 1024;
            #pragma unroll
            for (int i = 0; i < 8; i++) {
                const int idx = i * 128 + tid;
                const int fs = idx >> 6, r = idx & 63;
                cpa16(ksd + (fs * KSLD + r) * 16, gK + tb + idx);
                cpa16(vsd + (fs * VSLD + r) * 16, gV + tb + idx);
            }
            asm volatile("cp.async.commit_group;");
            asm volatile("cp.async.wait_group 1;");
        } else {
            asm volatile("cp.async.wait_group 0;");
        }
        __syncthreads();

        const uint4*  Kb = Ks + buf * (KBUF_BYTES / 16);
        const float4* Vb = Vs + buf * (VBUF_BYTES / 16);

        // ---- S = Q K^T : 3xBF16 ----
        float s[8][4];
        #pragma unroll
        for (int nt = 0; nt < 8; nt++)
            #pragma unroll
            for (int i = 0; i < 4; i++) s[nt][i] = 0.0f;

        #pragma unroll
        for (int kk = 0; kk < 4; kk++) {
            #pragma unroll
            for (int nt = 0; nt < 8; nt++) {
                uint4 kb = Kb[(kk * 4 + t) * KSLD + nt * 8 + g];
                mma16(s[nt], qh[kk], kb.x, kb.y);
                mma16(s[nt], qh[kk], kb.z, kb.w);
                mma16(s[nt], ql[kk], kb.x, kb.y);
            }
        }

        // mask add
        const int kBase = kt * 64;
        #pragma unroll
        for (int nt = 0; nt < 8; nt++) {
            const int c = kBase + nt * 8 + 2 * t;
            const float mk0 = msk[c], mk1 = msk[c + 1];
            s[nt][0] += mk0; s[nt][1] += mk1;
            s[nt][2] += mk0; s[nt][3] += mk1;
        }

        // ---- online softmax ----
        float mx0 = -CUDART_INF_F, mx1 = -CUDART_INF_F;
        #pragma unroll
        for (int nt = 0; nt < 8; nt++) {
            mx0 = fmaxf(mx0, fmaxf(s[nt][0], s[nt][1]));
            mx1 = fmaxf(mx1, fmaxf(s[nt][2], s[nt][3]));
        }
        mx0 = fmaxf(mx0, __shfl_xor_sync(0xffffffffu, mx0, 1));
        mx0 = fmaxf(mx0, __shfl_xor_sync(0xffffffffu, mx0, 2));
        mx1 = fmaxf(mx1, __shfl_xor_sync(0xffffffffu, mx1, 1));
        mx1 = fmaxf(mx1, __shfl_xor_sync(0xffffffffu, mx1, 2));

        const float mn0 = fmaxf(m_run0, mx0);
        const float mn1 = fmaxf(m_run1, mx1);
        const float corr0 = __expf(m_run0 - mn0);
        const float corr1 = __expf(m_run1 - mn1);

        float sum0 = 0.0f, sum1 = 0.0f;
        #pragma unroll
        for (int nt = 0; nt < 8; nt++) {
            s[nt][0] = __expf(s[nt][0] - mn0); sum0 += s[nt][0];
            s[nt][1] = __expf(s[nt][1] - mn0); sum0 += s[nt][1];
            s[nt][2] = __expf(s[nt][2] - mn1); sum1 += s[nt][2];
            s[nt][3] = __expf(s[nt][3] - mn1); sum1 += s[nt][3];
        }
        sum0 += __shfl_xor_sync(0xffffffffu, sum0, 1);
        sum0 += __shfl_xor_sync(0xffffffffu, sum0, 2);
        sum1 += __shfl_xor_sync(0xffffffffu, sum1, 1);
        sum1 += __shfl_xor_sync(0xffffffffu, sum1, 2);

        l_run0 = l_run0 * corr0 + sum0;
        l_run1 = l_run1 * corr1 + sum1;
        m_run0 = mn0; m_run1 = mn1;

        #pragma unroll
        for (int nt = 0; nt < 8; nt++) {
            o[nt][0] *= corr0; o[nt][1] *= corr0;
            o[nt][2] *= corr1; o[nt][3] *= corr1;
        }

        // ---- PV: register-shuffle P relayout + 1xTF32 mma ----
        #pragma unroll
        for (int kk2 = 0; kk2 < 4; kk2++) {
            unsigned pa[2][4];
            #pragma unroll
            for (int half = 0; half < 2; half++) {
                float* ss = s[kk2 * 2 + half];
                float u0 = __shfl_sync(0xffffffffu, ss[0], sl0);
                float u1 = __shfl_sync(0xffffffffu, ss[1], sl0);
                float u2 = __shfl_sync(0xffffffffu, ss[2], sl0);
                float u3 = __shfl_sync(0xffffffffu, ss[3], sl0);
                float w0 = __shfl_sync(0xffffffffu, ss[0], sl1);
                float w1 = __shfl_sync(0xffffffffu, ss[1], sl1);
                float w2 = __shfl_sync(0xffffffffu, ss[2], sl1);
                float w3 = __shfl_sync(0xffffffffu, ss[3], sl1);
                pa[half][0] = f2tf(odd ? u1 : u0);   // P[g][t]
                pa[half][1] = f2tf(odd ? u3 : u2);   // P[g+8][t]
                pa[half][2] = f2tf(odd ? w1 : w0);   // P[g][t+4]
                pa[half][3] = f2tf(odd ? w3 : w2);   // P[g+8][t+4]
            }
            #pragma unroll
            for (int nt = 0; nt < 8; nt++) {
                float4 vv = Vb[(kk2 * 4 + t) * VSLD + nt * 8 + g];
                mma8(o[nt], pa[0], __float_as_uint(vv.x), __float_as_uint(vv.y));
                mma8(o[nt], pa[1], __float_as_uint(vv.z), __float_as_uint(vv.w));
            }
        }
        __syncthreads();   // all warps done with buf before next issue overwrites
        buf ^= 1;
    }

    // ---- finalize ----
    const float inv0 = 1.0f / l_run0;
    const float inv1 = 1.0f / l_run1;
    const int q0 = qBase + qr;
    #pragma unroll
    for (int nt = 0; nt < 8; nt++) {
        const int d = h * 64 + nt * 8 + 2 * t;
        float2 v0 = make_float2(o[nt][0] * inv0, o[nt][1] * inv0);
        float2 v1 = make_float2(o[nt][2] * inv1, o[nt][3] * inv1);
        *(float2*)&out[((size_t)(b * S_ + q0    )) * D_ + d] = v0;
        *(float2*)&out[((size_t)(b * S_ + q0 + 8)) * D_ + d] = v1;
    }
}

// ---------------------------------------------------------------------------
extern "C" void kernel_launch(void* const* d_in, const int* in_sizes, int n_in,
                              void* d_out, int out_size)
{
    const float* X    = (const float*)d_in[0];
    const float* mask = (const float*)d_in[1];
    const float* Wq   = (const float*)d_in[2];
    const float* bq   = (const float*)d_in[3];
    const float* Wk   = (const float*)d_in[4];
    const float* bk   = (const float*)d_in[5];
    const float* Wv   = (const float*)d_in[6];
    const float* bv   = (const float*)d_in[7];
    float* out = (float*)d_out;

    {
        dim3 grid(D_ / 128, (B_ * S_) / 128, 3);
        qkv_kernel<<<grid, 256>>>(X, Wq, Wk, Wv, bq, bk, bv);
    }
    {
        dim3 grid(NT_, B_ * H_);
        pack_kernel<<<grid, 256>>>();
    }
    {
        const int smem = 2 * KBUF_BYTES + 2 * VBUF_BYTES + 2048 * 4;  // 75776
        cudaFuncSetAttribute(attn_kernel,
                             cudaFuncAttributeMaxDynamicSharedMemorySize, smem);
        dim3 grid(S_ / 64, B_ * H_);
        attn_kernel<<<grid, 128, smem>>>(mask, out);
    }
}

// round 7
// speedup vs baseline: 3.8118x; 1.0449x over previous
#include <cuda_runtime.h>
#include <cuda_bf16.h>
#include <math_constants.h>

#define B_  2
#define S_  2048
#define D_  1024
#define H_  16
#define HD_ 64
#define NT_ 32   // S_/64 tiles
#define KT_ 64   // D_/16 k-tiles for qkv

__device__ float g_Q[B_ * H_ * S_ * HD_];
__device__ float g_K[B_ * H_ * S_ * HD_];
__device__ float g_V[B_ * H_ * S_ * HD_];
// attention packed operands
__device__ uint4  g_Kp[B_ * H_ * NT_ * 16 * 64];
__device__ float4 g_Vp[B_ * H_ * NT_ * 16 * 64];
// qkv packed operands: X a-frags [kt][mG(256)][h(2)][lane(32)]
__device__ uint4  g_Xp[KT_ * 256 * 2 * 32];
// W b-frags [z][kt][n(1024)][t(4)] = {bh0,bh1,bl0,bl1}
__device__ uint4  g_Wp[3 * KT_ * 1024 * 4];

__device__ __forceinline__ unsigned f2tf(float x) {
    unsigned r;
    asm("cvt.rna.tf32.f32 %0, %1;" : "=r"(r) : "f"(x));
    return r;
}
__device__ __forceinline__ float tf2f(unsigned u) { return __uint_as_float(u); }
__device__ __forceinline__ float tfr(float x) { return tf2f(f2tf(x)); }
__device__ __forceinline__ float bfhi(float x) {
    return __bfloat162float(__float2bfloat16_rn(x));
}
__device__ __forceinline__ unsigned packbf(float a, float b) {
    __nv_bfloat162 h = __floats2bfloat162_rn(a, b);
    return *(unsigned*)&h;
}
__device__ __forceinline__ void mma8(float c[4], const unsigned a[4],
                                     unsigned b0, unsigned b1) {
    asm volatile(
        "mma.sync.aligned.m16n8k8.row.col.f32.tf32.tf32.f32 "
        "{%0,%1,%2,%3},{%4,%5,%6,%7},{%8,%9},{%0,%1,%2,%3};"
        : "+f"(c[0]), "+f"(c[1]), "+f"(c[2]), "+f"(c[3])
        : "r"(a[0]), "r"(a[1]), "r"(a[2]), "r"(a[3]), "r"(b0), "r"(b1));
}
__device__ __forceinline__ void mma16(float c[4], const unsigned a[4],
                                      unsigned b0, unsigned b1) {
    asm volatile(
        "mma.sync.aligned.m16n8k16.row.col.f32.bf16.bf16.f32 "
        "{%0,%1,%2,%3},{%4,%5,%6,%7},{%8,%9},{%0,%1,%2,%3};"
        : "+f"(c[0]), "+f"(c[1]), "+f"(c[2]), "+f"(c[3])
        : "r"(a[0]), "r"(a[1]), "r"(a[2]), "r"(a[3]), "r"(b0), "r"(b1));
}
__device__ __forceinline__ void cpa16(unsigned dst, const void* src) {
    asm volatile("cp.async.cg.shared.global [%0], [%1], 16;" :: "r"(dst), "l"(src));
}

// ---------------------------------------------------------------------------
// pack_x: X -> bf16 hi/lo a-frags. One thread = one (kt, mG, lane) frag pair.
// ---------------------------------------------------------------------------
__global__ __launch_bounds__(256) void pack_x_kernel(const float* __restrict__ X)
{
    const int id = blockIdx.x * 256 + threadIdx.x;   // 64*256*32 total
    const int lane = id & 31;
    const int t = lane & 3, g = lane >> 2;
    const int mG = (id >> 5) & 255;
    const int kt = id >> 13;
    const int m  = mG * 16 + g;
    const int c0 = kt * 16 + 2 * t;

    float2 x00 = *(const float2*)&X[(size_t)m * D_ + c0];
    float2 x01 = *(const float2*)&X[(size_t)m * D_ + c0 + 8];
    float2 x10 = *(const float2*)&X[(size_t)(m + 8) * D_ + c0];
    float2 x11 = *(const float2*)&X[(size_t)(m + 8) * D_ + c0 + 8];

    float h00 = bfhi(x00.x), h01 = bfhi(x00.y);
    float h10 = bfhi(x10.x), h11 = bfhi(x10.y);
    float h02 = bfhi(x01.x), h03 = bfhi(x01.y);
    float h12 = bfhi(x11.x), h13 = bfhi(x11.y);

    uint4 hi, lo;
    hi.x = packbf(h00, h01);             hi.y = packbf(h10, h11);
    hi.z = packbf(h02, h03);             hi.w = packbf(h12, h13);
    lo.x = packbf(x00.x - h00, x00.y - h01);
    lo.y = packbf(x10.x - h10, x10.y - h11);
    lo.z = packbf(x01.x - h02, x01.y - h03);
    lo.w = packbf(x11.x - h12, x11.y - h13);

    const size_t base = ((size_t)kt * 256 + mG) * 64;
    g_Xp[base + lane]      = hi;
    g_Xp[base + 32 + lane] = lo;
}

// ---------------------------------------------------------------------------
// pack_w: Wq/Wk/Wv -> uint4 b-frags {bh0,bh1,bl0,bl1} at [z][kt][n][t].
// ---------------------------------------------------------------------------
__global__ __launch_bounds__(256) void pack_w_kernel(
    const float* __restrict__ Wq, const float* __restrict__ Wk, const float* __restrict__ Wv)
{
    const int id = blockIdx.x * 256 + threadIdx.x;   // 3*64*1024*4 total
    const int t  = id & 3;
    const int n  = (id >> 2) & 1023;
    const int kt = (id >> 12) & 63;
    const int z  = id >> 18;
    const float* W = (z == 0) ? Wq : (z == 1) ? Wk : Wv;
    const int k0 = kt * 16;

    float w0 = W[(size_t)(k0 + 2*t    ) * D_ + n];
    float w1 = W[(size_t)(k0 + 2*t + 1) * D_ + n];
    float w2 = W[(size_t)(k0 + 2*t + 8) * D_ + n];
    float w3 = W[(size_t)(k0 + 2*t + 9) * D_ + n];
    float h0 = bfhi(w0), h1 = bfhi(w1), h2 = bfhi(w2), h3 = bfhi(w3);

    uint4 frag;
    frag.x = packbf(h0, h1);
    frag.y = packbf(h2, h3);
    frag.z = packbf(w0 - h0, w1 - h1);
    frag.w = packbf(w2 - h2, w3 - h3);
    g_Wp[id] = frag;
}

// ---------------------------------------------------------------------------
// QKV projection: pure-copy mainloop. cp.async double-buffered packed frags,
// 12 LDS.128 + 48 mma16 per k16 iter. 256 threads = 8 warps (4m x 2n).
// ---------------------------------------------------------------------------
__global__ __launch_bounds__(256) void qkv_kernel(
    const float* __restrict__ bq, const float* __restrict__ bk, const float* __restrict__ bv)
{
    const int z = blockIdx.z;
    const float* bias = (z == 0) ? bq : (z == 1) ? bk : bv;
    float* Out        = (z == 0) ? g_Q : (z == 1) ? g_K : g_V;
    const float scale = (z == 0) ? 0.125f : 1.0f;

    // per buffer: A frags 512 u4 (8KB) + B frags 512 u4 (8KB)
    __shared__ uint4 sm[2 * 1024];
    unsigned sm_base;
    {
        void* p = sm;
        asm("{ .reg .u64 tmp; cvta.to.shared.u64 tmp, %1; cvt.u32.u64 %0, tmp; }"
            : "=r"(sm_base) : "l"(p));
    }

    const int tid  = threadIdx.x;
    const int lane = tid & 31;
    const int warp = tid >> 5;
    const int wm = warp & 3;
    const int wn = warp >> 2;
    const int rowBase = blockIdx.y * 128;
    const int colBase = blockIdx.x * 128;
    const int g = lane >> 2;
    const int t = lane & 3;

    const uint4* gX = g_Xp + (size_t)(rowBase >> 4) * 64;          // + kt*16384 + j
    const uint4* gW = g_Wp + (size_t)z * (KT_ * 4096) + colBase * 4; // + kt*4096 + j

    float acc[2][8][4];
    #pragma unroll
    for (int mt = 0; mt < 2; mt++)
        #pragma unroll
        for (int nt = 0; nt < 8; nt++)
            #pragma unroll
            for (int i = 0; i < 4; i++) acc[mt][nt][i] = 0.0f;

    // prologue: tile 0 -> buffer 0
    #pragma unroll
    for (int i = 0; i < 4; i++) {
        const int j = i * 256 + tid;   // 0..1023: first 512 = A, next 512 = B
        if (j < 512) cpa16(sm_base + j * 16, gX + j);
        else         cpa16(sm_base + j * 16, gW + (j - 512));
    }
    asm volatile("cp.async.commit_group;");

    int buf = 0;
    for (int kt = 0; kt < KT_; kt++) {
        if (kt + 1 < KT_) {
            const unsigned dst = sm_base + (buf ^ 1) * 16384;
            const size_t xo = (size_t)(kt + 1) * 16384;
            const size_t wo = (size_t)(kt + 1) * 4096;
            #pragma unroll
            for (int i = 0; i < 4; i++) {
                const int j = i * 256 + tid;
                if (j < 512) cpa16(dst + j * 16, gX + xo + j);
                else         cpa16(dst + j * 16, gW + wo + (j - 512));
            }
            asm volatile("cp.async.commit_group;");
            asm volatile("cp.async.wait_group 1;");
        } else {
            asm volatile("cp.async.wait_group 0;");
        }
        __syncthreads();

        const uint4* As = sm + buf * 1024;
        const uint4* Bs = As + 512;

        unsigned ah[2][4], al[2][4];
        #pragma unroll
        for (int mt = 0; mt < 2; mt++) {
            uint4 h4 = As[(wm * 2 + mt) * 64 + lane];
            uint4 l4 = As[(wm * 2 + mt) * 64 + 32 + lane];
            ah[mt][0] = h4.x; ah[mt][1] = h4.y; ah[mt][2] = h4.z; ah[mt][3] = h4.w;
            al[mt][0] = l4.x; al[mt][1] = l4.y; al[mt][2] = l4.z; al[mt][3] = l4.w;
        }
        #pragma unroll
        for (int nt = 0; nt < 8; nt++) {
            uint4 bb = Bs[(wn * 64 + nt * 8 + g) * 4 + t];
            #pragma unroll
            for (int mt = 0; mt < 2; mt++) {
                mma16(acc[mt][nt], ah[mt], bb.x, bb.y);
                mma16(acc[mt][nt], ah[mt], bb.z, bb.w);
                mma16(acc[mt][nt], al[mt], bb.x, bb.y);
            }
        }
        __syncthreads();
        buf ^= 1;
    }

    // epilogue: bias, scale, scatter to [B,H,S,HD]
    #pragma unroll
    for (int mt = 0; mt < 2; mt++) {
        #pragma unroll
        for (int nt = 0; nt < 8; nt++) {
            const int n0 = colBase + wn * 64 + nt * 8 + 2 * t;
            #pragma unroll
            for (int i = 0; i < 4; i++) {
                const int m = rowBase + wm * 32 + mt * 16 + g + ((i >> 1) ? 8 : 0);
                const int n = n0 + (i & 1);
                const int b = m >> 11;
                const int s = m & (S_ - 1);
                const int h = n >> 6;
                const int d = n & (HD_ - 1);
                Out[(((size_t)(b * H_ + h) * S_) + s) * HD_ + d] =
                    (acc[mt][nt][i] + bias[n]) * scale;
            }
        }
    }
}

// ---------------------------------------------------------------------------
// Pack kernel (attn): K -> bf16 hi/lo uint4 frags, V -> transposed tf32 float4.
// ---------------------------------------------------------------------------
__global__ __launch_bounds__(256) void pack_kernel()
{
    const int kt = blockIdx.x;
    const int bh = blockIdx.y;
    const int tid = threadIdx.x;
    const size_t tile = (size_t)(bh * NT_ + kt) * 16 * 64;

    if (tid < 128) {
        const int r  = tid & 63;
        const int kh = tid >> 6;
        const float* Kr = g_K + ((size_t)bh * S_ + kt * 64 + r) * HD_ + kh * 32;
        float f[32];
        #pragma unroll
        for (int i = 0; i < 8; i++)
            *(float4*)&f[i * 4] = *(const float4*)&Kr[i * 4];
        #pragma unroll
        for (int q = 0; q < 2; q++) {
            const int kk = 2 * kh + q;
            #pragma unroll
            for (int tt = 0; tt < 4; tt++) {
                float a0 = f[q*16 + 2*tt],     a1 = f[q*16 + 2*tt + 1];
                float a2 = f[q*16 + 2*tt + 8], a3 = f[q*16 + 2*tt + 9];
                float h0 = bfhi(a0), h1 = bfhi(a1), h2 = bfhi(a2), h3 = bfhi(a3);
                uint4 frag;
                frag.x = packbf(h0, h1);
                frag.y = packbf(h2, h3);
                frag.z = packbf(a0 - h0, a1 - h1);
                frag.w = packbf(a2 - h2, a3 - h3);
                g_Kp[tile + (size_t)(kk * 4 + tt) * 64 + r] = frag;
            }
        }
    } else {
        const int j  = tid - 128;
        const int d  = j & 63;
        const int ph = j >> 6;
        const float* Vb = g_V + ((size_t)bh * S_ + kt * 64) * HD_;
        #pragma unroll
        for (int pi = 0; pi < 8; pi++) {
            const int pslot = ph * 8 + pi;
            const int kk2 = pslot >> 2, t = pslot & 3;
            const int k0 = kk2 * 16 + t;
            float4 v;
            v.x = tfr(Vb[(size_t)(k0     ) * HD_ + d]);
            v.y = tfr(Vb[(size_t)(k0 +  4) * HD_ + d]);
            v.z = tfr(Vb[(size_t)(k0 +  8) * HD_ + d]);
            v.w = tfr(Vb[(size_t)(k0 + 12) * HD_ + d]);
            g_Vp[tile + (size_t)pslot * 64 + d] = v;
        }
    }
}

// ---------------------------------------------------------------------------
// Flash attention (unchanged from R6).
// ---------------------------------------------------------------------------
#define KSLD 66
#define VSLD 66
#define KBUF_BYTES (16 * KSLD * 16)
#define VBUF_BYTES (16 * VSLD * 16)
__global__ __launch_bounds__(128) void attn_kernel(
    const float* __restrict__ mask, float* __restrict__ out)
{
    extern __shared__ char smc[];
    uint4*  Ks   = (uint4*)smc;
    float4* Vs   = (float4*)(smc + 2 * KBUF_BYTES);
    float*  msk  = (float*)(smc + 2 * KBUF_BYTES + 2 * VBUF_BYTES);
    float*  Qst  = (float*)(smc + 2 * KBUF_BYTES);

    const int tid  = threadIdx.x;
    const int lane = tid & 31;
    const int warp = tid >> 5;
    const int g = lane >> 2;
    const int t = lane & 3;
    const int qBase = blockIdx.x * 64;
    const int bh = blockIdx.y;
    const int b = bh >> 4;
    const int h = bh & 15;

    unsigned smem_base;
    {
        void* p = smc;
        asm("{ .reg .u64 tmp; cvta.to.shared.u64 tmp, %1; cvt.u32.u64 %0, tmp; }"
            : "=r"(smem_base) : "l"(p));
    }
    const unsigned ks_sm = smem_base;
    const unsigned vs_sm = smem_base + 2 * KBUF_BYTES;

    #pragma unroll
    for (int i = 0; i < 4; i++) {
        const int idx = i * 128 + tid;
        ((float4*)msk)[idx] = ((const float4*)(mask + (size_t)b * S_))[idx];
    }
    const float* Qp = g_Q + (size_t)bh * S_ * HD_;
    #pragma unroll
    for (int i = 0; i < 8; i++) {
        const int idx = i * 128 + tid;
        const int r = idx >> 4, c = idx & 15;
        *(float4*)&Qst[r * 68 + c * 4] = *(const float4*)&Qp[(size_t)(qBase + r) * HD_ + c * 4];
    }
    __syncthreads();

    unsigned qh[4][4], ql[4][4];
    const int qr = warp * 16 + g;
    #pragma unroll
    for (int kk = 0; kk < 4; kk++) {
        const int c0 = kk * 16 + 2 * t;
        float q00 = Qst[ qr      * 68 + c0], q01 = Qst[ qr      * 68 + c0 + 1];
        float q10 = Qst[(qr + 8) * 68 + c0], q11 = Qst[(qr + 8) * 68 + c0 + 1];
        float q02 = Qst[ qr      * 68 + c0 + 8], q03 = Qst[ qr      * 68 + c0 + 9];
        float q12 = Qst[(qr + 8) * 68 + c0 + 8], q13 = Qst[(qr + 8) * 68 + c0 + 9];
        float h00 = bfhi(q00), h01 = bfhi(q01), h10 = bfhi(q10), h11 = bfhi(q11);
        float h02 = bfhi(q02), h03 = bfhi(q03), h12 = bfhi(q12), h13 = bfhi(q13);
        qh[kk][0] = packbf(h00, h01);             qh[kk][1] = packbf(h10, h11);
        qh[kk][2] = packbf(h02, h03);             qh[kk][3] = packbf(h12, h13);
        ql[kk][0] = packbf(q00 - h00, q01 - h01); ql[kk][1] = packbf(q10 - h10, q11 - h11);
        ql[kk][2] = packbf(q02 - h02, q03 - h03); ql[kk][3] = packbf(q12 - h12, q13 - h13);
    }
    __syncthreads();

    const uint4*  gK = g_Kp + (size_t)bh * NT_ * 1024;
    const float4* gV = g_Vp + (size_t)bh * NT_ * 1024;

    #pragma unroll
    for (int i = 0; i < 8; i++) {
        const int idx = i * 128 + tid;
        const int fs = idx >> 6, r = idx & 63;
        cpa16(ks_sm + (fs * KSLD + r) * 16, gK + idx);
        cpa16(vs_sm + (fs * VSLD + r) * 16, gV + idx);
    }
    asm volatile("cp.async.commit_group;");

    float m_run0 = -CUDART_INF_F, m_run1 = -CUDART_INF_F;
    float l_run0 = 0.0f, l_run1 = 0.0f;
    float o[8][4];
    #pragma unroll
    for (int nt = 0; nt < 8; nt++)
        #pragma unroll
        for (int i = 0; i < 4; i++) o[nt][i] = 0.0f;

    const int bl  = lane & 28;
    const int sl0 = bl + (t >> 1);
    const int sl1 = sl0 + 2;
    const bool odd = (t & 1);

    int buf = 0;
    for (int kt = 0; kt < NT_; kt++) {
        if (kt + 1 < NT_) {
            const unsigned ksd = ks_sm + (buf ^ 1) * KBUF_BYTES;
            const unsigned vsd = vs_sm + (buf ^ 1) * VBUF_BYTES;
            const size_t tb = (size_t)(kt + 1) * 1024;
            #pragma unroll
            for (int i = 0; i < 8; i++) {
                const int idx = i * 128 + tid;
                const int fs = idx >> 6, r = idx & 63;
                cpa16(ksd + (fs * KSLD + r) * 16, gK + tb + idx);
                cpa16(vsd + (fs * VSLD + r) * 16, gV + tb + idx);
            }
            asm volatile("cp.async.commit_group;");
            asm volatile("cp.async.wait_group 1;");
        } else {
            asm volatile("cp.async.wait_group 0;");
        }
        __syncthreads();

        const uint4*  Kb = Ks + buf * (KBUF_BYTES / 16);
        const float4* Vb = Vs + buf * (VBUF_BYTES / 16);

        float s[8][4];
        #pragma unroll
        for (int nt = 0; nt < 8; nt++)
            #pragma unroll
            for (int i = 0; i < 4; i++) s[nt][i] = 0.0f;

        #pragma unroll
        for (int kk = 0; kk < 4; kk++) {
            #pragma unroll
            for (int nt = 0; nt < 8; nt++) {
                uint4 kb = Kb[(kk * 4 + t) * KSLD + nt * 8 + g];
                mma16(s[nt], qh[kk], kb.x, kb.y);
                mma16(s[nt], qh[kk], kb.z, kb.w);
                mma16(s[nt], ql[kk], kb.x, kb.y);
            }
        }

        const int kBase = kt * 64;
        #pragma unroll
        for (int nt = 0; nt < 8; nt++) {
            const int c = kBase + nt * 8 + 2 * t;
            const float mk0 = msk[c], mk1 = msk[c + 1];
            s[nt][0] += mk0; s[nt][1] += mk1;
            s[nt][2] += mk0; s[nt][3] += mk1;
        }

        float mx0 = -CUDART_INF_F, mx1 = -CUDART_INF_F;
        #pragma unroll
        for (int nt = 0; nt < 8; nt++) {
            mx0 = fmaxf(mx0, fmaxf(s[nt][0], s[nt][1]));
            mx1 = fmaxf(mx1, fmaxf(s[nt][2], s[nt][3]));
        }
        mx0 = fmaxf(mx0, __shfl_xor_sync(0xffffffffu, mx0, 1));
        mx0 = fmaxf(mx0, __shfl_xor_sync(0xffffffffu, mx0, 2));
        mx1 = fmaxf(mx1, __shfl_xor_sync(0xffffffffu, mx1, 1));
        mx1 = fmaxf(mx1, __shfl_xor_sync(0xffffffffu, mx1, 2));

        const float mn0 = fmaxf(m_run0, mx0);
        const float mn1 = fmaxf(m_run1, mx1);
        const float corr0 = __expf(m_run0 - mn0);
        const float corr1 = __expf(m_run1 - mn1);

        float sum0 = 0.0f, sum1 = 0.0f;
        #pragma unroll
        for (int nt = 0; nt < 8; nt++) {
            s[nt][0] = __expf(s[nt][0] - mn0); sum0 += s[nt][0];
            s[nt][1] = __expf(s[nt][1] - mn0); sum0 += s[nt][1];
            s[nt][2] = __expf(s[nt][2] - mn1); sum1 += s[nt][2];
            s[nt][3] = __expf(s[nt][3] - mn1); sum1 += s[nt][3];
        }
        sum0 += __shfl_xor_sync(0xffffffffu, sum0, 1);
        sum0 += __shfl_xor_sync(0xffffffffu, sum0, 2);
        sum1 += __shfl_xor_sync(0xffffffffu, sum1, 1);
        sum1 += __shfl_xor_sync(0xffffffffu, sum1, 2);

        l_run0 = l_run0 * corr0 + sum0;
        l_run1 = l_run1 * corr1 + sum1;
        m_run0 = mn0; m_run1 = mn1;

        #pragma unroll
        for (int nt = 0; nt < 8; nt++) {
            o[nt][0] *= corr0; o[nt][1] *= corr0;
            o[nt][2] *= corr1; o[nt][3] *= corr1;
        }

        #pragma unroll
        for (int kk2 = 0; kk2 < 4; kk2++) {
            unsigned pa[2][4];
            #pragma unroll
            for (int half = 0; half < 2; half++) {
                float* ss = s[kk2 * 2 + half];
                float u0 = __shfl_sync(0xffffffffu, ss[0], sl0);
                float u1 = __shfl_sync(0xffffffffu, ss[1], sl0);
                float u2 = __shfl_sync(0xffffffffu, ss[2], sl0);
                float u3 = __shfl_sync(0xffffffffu, ss[3], sl0);
                float w0 = __shfl_sync(0xffffffffu, ss[0], sl1);
                float w1 = __shfl_sync(0xffffffffu, ss[1], sl1);
                float w2 = __shfl_sync(0xffffffffu, ss[2], sl1);
                float w3 = __shfl_sync(0xffffffffu, ss[3], sl1);
                pa[half][0] = f2tf(odd ? u1 : u0);
                pa[half][1] = f2tf(odd ? u3 : u2);
                pa[half][2] = f2tf(odd ? w1 : w0);
                pa[half][3] = f2tf(odd ? w3 : w2);
            }
            #pragma unroll
            for (int nt = 0; nt < 8; nt++) {
                float4 vv = Vb[(kk2 * 4 + t) * VSLD + nt * 8 + g];
                mma8(o[nt], pa[0], __float_as_uint(vv.x), __float_as_uint(vv.y));
                mma8(o[nt], pa[1], __float_as_uint(vv.z), __float_as_uint(vv.w));
            }
        }
        __syncthreads();
        buf ^= 1;
    }

    const float inv0 = 1.0f / l_run0;
    const float inv1 = 1.0f / l_run1;
    const int q0 = qBase + qr;
    #pragma unroll
    for (int nt = 0; nt < 8; nt++) {
        const int d = h * 64 + nt * 8 + 2 * t;
        float2 v0 = make_float2(o[nt][0] * inv0, o[nt][1] * inv0);
        float2 v1 = make_float2(o[nt][2] * inv1, o[nt][3] * inv1);
        *(float2*)&out[((size_t)(b * S_ + q0    )) * D_ + d] = v0;
        *(float2*)&out[((size_t)(b * S_ + q0 + 8)) * D_ + d] = v1;
    }
}

// ---------------------------------------------------------------------------
extern "C" void kernel_launch(void* const* d_in, const int* in_sizes, int n_in,
                              void* d_out, int out_size)
{
    const float* X    = (const float*)d_in[0];
    const float* mask = (const float*)d_in[1];
    const float* Wq   = (const float*)d_in[2];
    const float* bq   = (const float*)d_in[3];
    const float* Wk   = (const float*)d_in[4];
    const float* bk   = (const float*)d_in[5];
    const float* Wv   = (const float*)d_in[6];
    const float* bv   = (const float*)d_in[7];
    float* out = (float*)d_out;

    pack_x_kernel<<<(KT_ * 256 * 32) / 256, 256>>>(X);
    pack_w_kernel<<<(3 * KT_ * 1024 * 4) / 256, 256>>>(Wq, Wk, Wv);
    {
        dim3 grid(D_ / 128, (B_ * S_) / 128, 3);
        qkv_kernel<<<grid, 256>>>(bq, bk, bv);
    }
    {
        dim3 grid(NT_, B_ * H_);
        pack_kernel<<<grid, 256>>>();
    }
    {
        const int smem = 2 * KBUF_BYTES + 2 * VBUF_BYTES + 2048 * 4;  // 75776
        cudaFuncSetAttribute(attn_kernel,
                             cudaFuncAttributeMaxDynamicSharedMemorySize, smem);
        dim3 grid(S_ / 64, B_ * H_);
        attn_kernel<<<grid, 128, smem>>>(mask, out);
    }
}